// round 16
// baseline (speedup 1.0000x reference)
#include <cuda_runtime.h>
#include <math.h>
#include <stdint.h>

#define BB 16
#define DD 512
#define HW 484
#define LE 1452
#define LDQ 484
#define NSCALE 0.011048543456039806f
#define DHWF 247808.0f
#define IEPS 1e-5f
#define GRP 247808
#define QF4 15488

#define SZ_PE     ((size_t)HW*DD)
#define SZ_LABEL  ((size_t)BB*LE)
#define SZ_XE     ((size_t)BB*LE*DD)
#define SZ_DX0    ((size_t)96*LDQ*DD)
#define SZ_PQ     ((size_t)BB*LE*128)
#define SZ_DPQ    ((size_t)96*LDQ*128)
#define SZ_DMASK  ((size_t)96*LDQ)
#define SZ_PROBS  ((size_t)96*LDQ*1456)

#define OFF_PE    ((size_t)0)
#define OFF_LABEL (OFF_PE + SZ_PE)
#define OFF_XE    (OFF_LABEL + SZ_LABEL)
#define OFF_DX0   (OFF_XE + SZ_XE)          // [xe|dx0] contiguous (self proj in)
#define OFF_PQ    (OFF_DX0 + SZ_DX0)
#define OFF_DPQ   (OFF_PQ + SZ_PQ)          // [pq|dpq] contiguous (self proj out)
#define OFF_X1E   (OFF_DPQ + SZ_DPQ)
#define OFF_DX1   (OFF_X1E + SZ_XE)         // [x1e|dx1] contiguous (cross proj in)
#define OFF_PKC   (OFF_DX1 + SZ_DX0)
#define OFF_DPQ2  (OFF_PKC + SZ_PQ)         // [pkc|dpq2] contiguous (cross proj out)
#define OFF_DXPT3 (OFF_DPQ2 + SZ_DPQ)
#define OFF_DMASK (OFF_DXPT3 + SZ_DX0)
#define OFF_DSC   (OFF_DMASK + SZ_DMASK)
#define OFF_IPART (OFF_DSC + 96*4)
#define OFF_DPARTI (OFF_IPART + 48*4)
#define OFF_DPART3 (OFF_DPARTI + 96*4)
#define OFF_SC144 (OFF_DPART3 + 96*4*3)
#define OFF_PROBS (OFF_SC144 + 144)
#define SCRATCH_TOTAL (OFF_PROBS + SZ_PROBS)

__device__ __align__(16) float g_scratch[SCRATCH_TOTAL];

__device__ __forceinline__ uint32_t f2tf32(float f) {
    uint32_t u;
    asm("cvt.rna.tf32.f32 %0, %1;" : "=r"(u) : "f"(f));
    return u;
}
__device__ __forceinline__ void mma_tf32(float* c, uint32_t a0, uint32_t a1,
                                         uint32_t a2, uint32_t a3,
                                         uint32_t b0, uint32_t b1) {
    asm volatile("mma.sync.aligned.m16n8k8.row.col.f32.tf32.tf32.f32 "
                 "{%0,%1,%2,%3}, {%4,%5,%6,%7}, {%8,%9}, {%0,%1,%2,%3};"
                 : "+f"(c[0]), "+f"(c[1]), "+f"(c[2]), "+f"(c[3])
                 : "r"(a0), "r"(a1), "r"(a2), "r"(a3), "r"(b0), "r"(b1));
}
__device__ __forceinline__ void ld8(const float* p, bool valid, float* r) {
    if (valid) {
        float4 v0 = *(const float4*)p;
        float4 v1 = *(const float4*)(p + 4);
        r[0] = v0.x; r[1] = v0.y; r[2] = v0.z; r[3] = v0.w;
        r[4] = v1.x; r[5] = v1.y; r[6] = v1.z; r[7] = v1.w;
    } else {
#pragma unroll
        for (int j = 0; j < 8; j++) r[j] = 0.0f;
    }
}

// ============ tf32 projection GEMM (NT, K=512, N=128) + bias + L2norm ======
// ASCALE (optional): per-row scale ASCALE[row/484] applied to A during staging.
__global__ void __launch_bounds__(256, 2)
tf32_proj_kernel(const float* __restrict__ A, const float* __restrict__ W,
                 float* __restrict__ C, const float* __restrict__ BIAS,
                 const float* __restrict__ ASCALE, int M) {
    __shared__ __align__(16) uint32_t As[2][128][20];
    __shared__ __align__(16) uint32_t Bs[2][128][20];
    __shared__ float ssq[128][4];
    int mBase = blockIdx.y * 128;
    int t = threadIdx.x, lane = t & 31, warp = t >> 5;
    int mW = (warp >> 2) * 64, nW = (warp & 3) * 32;

    int rr = t >> 1, kc = (t & 1) * 8;
    int arow = mBase + rr;
    bool avalid = arow < M;
    float asc = 1.0f;
    if (ASCALE && avalid) asc = ASCALE[arow / 484];
    const float* aPtr = A + (size_t)arow * 512 + kc;
    const float* bPtr = W + (size_t)rr * 512 + kc;

    float ra[8], rb[8];
    ld8(aPtr, avalid, ra);
    ld8(bPtr, true, rb);
    {
        uint32_t ua[8], ub[8];
#pragma unroll
        for (int j = 0; j < 8; j++) { ua[j] = f2tf32(ra[j] * asc); ub[j] = f2tf32(rb[j]); }
        *(uint4*)&As[0][rr][kc]     = make_uint4(ua[0], ua[1], ua[2], ua[3]);
        *(uint4*)&As[0][rr][kc + 4] = make_uint4(ua[4], ua[5], ua[6], ua[7]);
        *(uint4*)&Bs[0][rr][kc]     = make_uint4(ub[0], ub[1], ub[2], ub[3]);
        *(uint4*)&Bs[0][rr][kc + 4] = make_uint4(ub[4], ub[5], ub[6], ub[7]);
    }
    __syncthreads();

    float acc[4][4][4];
#pragma unroll
    for (int i = 0; i < 4; i++)
#pragma unroll
        for (int j = 0; j < 4; j++)
#pragma unroll
            for (int q = 0; q < 4; q++) acc[i][j][q] = 0.0f;

    int buf = 0;
    int lr = lane >> 2, lc = lane & 3;

    for (int k0 = 0; k0 < 512; k0 += 16) {
        int kn = k0 + 16;
        bool more = kn < 512;
        if (more) {
            ld8(aPtr + kn, avalid, ra);
            ld8(bPtr + kn, true, rb);
        }
#pragma unroll
        for (int ks = 0; ks < 16; ks += 8) {
            uint32_t bf[4][2];
#pragma unroll
            for (int nt = 0; nt < 4; nt++) {
                int nn = nW + nt * 8 + lr;
                bf[nt][0] = Bs[buf][nn][ks + lc];
                bf[nt][1] = Bs[buf][nn][ks + lc + 4];
            }
#pragma unroll
            for (int mt = 0; mt < 4; mt++) {
                int r = mW + mt * 16 + lr;
                uint32_t a0 = As[buf][r][ks + lc];
                uint32_t a1 = As[buf][r + 8][ks + lc];
                uint32_t a2 = As[buf][r][ks + lc + 4];
                uint32_t a3 = As[buf][r + 8][ks + lc + 4];
#pragma unroll
                for (int nt = 0; nt < 4; nt++)
                    mma_tf32(acc[mt][nt], a0, a1, a2, a3, bf[nt][0], bf[nt][1]);
            }
        }
        if (more) {
            int nb = buf ^ 1;
            uint32_t ua[8], ub[8];
#pragma unroll
            for (int j = 0; j < 8; j++) { ua[j] = f2tf32(ra[j] * asc); ub[j] = f2tf32(rb[j]); }
            *(uint4*)&As[nb][rr][kc]     = make_uint4(ua[0], ua[1], ua[2], ua[3]);
            *(uint4*)&As[nb][rr][kc + 4] = make_uint4(ua[4], ua[5], ua[6], ua[7]);
            *(uint4*)&Bs[nb][rr][kc]     = make_uint4(ub[0], ub[1], ub[2], ub[3]);
            *(uint4*)&Bs[nb][rr][kc + 4] = make_uint4(ub[4], ub[5], ub[6], ub[7]);
            __syncthreads();
            buf = nb;
        }
    }

    float bv[4][2];
#pragma unroll
    for (int nt = 0; nt < 4; nt++) {
        bv[nt][0] = BIAS[nW + nt * 8 + lc * 2];
        bv[nt][1] = BIAS[nW + nt * 8 + lc * 2 + 1];
    }
#pragma unroll
    for (int mt = 0; mt < 4; mt++) {
        float p1 = 0.0f, p2 = 0.0f;
#pragma unroll
        for (int nt = 0; nt < 4; nt++) {
            acc[mt][nt][0] += bv[nt][0];
            acc[mt][nt][1] += bv[nt][1];
            acc[mt][nt][2] += bv[nt][0];
            acc[mt][nt][3] += bv[nt][1];
            p1 += acc[mt][nt][0] * acc[mt][nt][0] + acc[mt][nt][1] * acc[mt][nt][1];
            p2 += acc[mt][nt][2] * acc[mt][nt][2] + acc[mt][nt][3] * acc[mt][nt][3];
        }
        p1 += __shfl_xor_sync(0xffffffffu, p1, 1);
        p1 += __shfl_xor_sync(0xffffffffu, p1, 2);
        p2 += __shfl_xor_sync(0xffffffffu, p2, 1);
        p2 += __shfl_xor_sync(0xffffffffu, p2, 2);
        if (lc == 0) {
            ssq[mW + mt * 16 + lr][warp & 3] = p1;
            ssq[mW + mt * 16 + lr + 8][warp & 3] = p2;
        }
    }
    __syncthreads();
#pragma unroll
    for (int mt = 0; mt < 4; mt++) {
        int l1 = mW + mt * 16 + lr, l2 = l1 + 8;
        float s1 = ssq[l1][0] + ssq[l1][1] + ssq[l1][2] + ssq[l1][3];
        float s2 = ssq[l2][0] + ssq[l2][1] + ssq[l2][2] + ssq[l2][3];
        float rn1 = 1.0f / fmaxf(sqrtf(s1), 1e-12f);
        float rn2 = 1.0f / fmaxf(sqrtf(s2), 1e-12f);
        int r1 = mBase + l1, r2 = mBase + l2;
#pragma unroll
        for (int nt = 0; nt < 4; nt++) {
            int cb = nW + nt * 8 + lc * 2;
            if (r1 < M)
                *(float2*)(C + (size_t)r1 * 128 + cb) =
                    make_float2(acc[mt][nt][0] * rn1, acc[mt][nt][1] * rn1);
            if (r2 < M)
                *(float2*)(C + (size_t)r2 * 128 + cb) =
                    make_float2(acc[mt][nt][2] * rn2, acc[mt][nt][3] * rn2);
        }
    }
}

// ============ tf32 logits GEMM (NT) + exp epilogue ============
__global__ void __launch_bounds__(256, 2)
tf32_logits_kernel(const float* __restrict__ PQ, const float* __restrict__ PK,
                   float* __restrict__ C, int M, int N, int ldC, int NVALID,
                   size_t sA, size_t sB, size_t sC, int gkMod) {
    __shared__ __align__(16) uint32_t As[2][128][20];
    __shared__ __align__(16) uint32_t Bs[2][128][20];
    int g = blockIdx.z;
    int gk = gkMod ? (g & 15) : g;
    const float* Ag = PQ + (size_t)g * sA;
    const float* Bg = PK + (size_t)gk * sB;
    int mBase = blockIdx.y * 128, nBase = blockIdx.x * 128;
    int t = threadIdx.x, lane = t & 31, warp = t >> 5;
    int mW = (warp >> 2) * 64, nW = (warp & 3) * 32;

    int rr = t >> 1, kc = (t & 1) * 8;
    bool avalid = (mBase + rr) < M;
    bool bvalid = (nBase + rr) < N;
    const float* aPtr = Ag + (size_t)(mBase + rr) * 128 + kc;
    const float* bPtr = Bg + (size_t)(nBase + rr) * 128 + kc;

    float ra[8], rb[8];
    ld8(aPtr, avalid, ra);
    ld8(bPtr, bvalid, rb);
    {
        uint32_t ua[8], ub[8];
#pragma unroll
        for (int j = 0; j < 8; j++) { ua[j] = f2tf32(ra[j]); ub[j] = f2tf32(rb[j]); }
        *(uint4*)&As[0][rr][kc]     = make_uint4(ua[0], ua[1], ua[2], ua[3]);
        *(uint4*)&As[0][rr][kc + 4] = make_uint4(ua[4], ua[5], ua[6], ua[7]);
        *(uint4*)&Bs[0][rr][kc]     = make_uint4(ub[0], ub[1], ub[2], ub[3]);
        *(uint4*)&Bs[0][rr][kc + 4] = make_uint4(ub[4], ub[5], ub[6], ub[7]);
    }
    __syncthreads();

    float acc[4][4][4];
#pragma unroll
    for (int i = 0; i < 4; i++)
#pragma unroll
        for (int j = 0; j < 4; j++)
#pragma unroll
            for (int q = 0; q < 4; q++) acc[i][j][q] = 0.0f;

    int buf = 0;
    int lr = lane >> 2, lc = lane & 3;

    for (int k0 = 0; k0 < 128; k0 += 16) {
        int kn = k0 + 16;
        bool more = kn < 128;
        if (more) {
            ld8(aPtr + kn, avalid, ra);
            ld8(bPtr + kn, bvalid, rb);
        }
#pragma unroll
        for (int ks = 0; ks < 16; ks += 8) {
            uint32_t bf[4][2];
#pragma unroll
            for (int nt = 0; nt < 4; nt++) {
                int nn = nW + nt * 8 + lr;
                bf[nt][0] = Bs[buf][nn][ks + lc];
                bf[nt][1] = Bs[buf][nn][ks + lc + 4];
            }
#pragma unroll
            for (int mt = 0; mt < 4; mt++) {
                int r = mW + mt * 16 + lr;
                uint32_t a0 = As[buf][r][ks + lc];
                uint32_t a1 = As[buf][r + 8][ks + lc];
                uint32_t a2 = As[buf][r][ks + lc + 4];
                uint32_t a3 = As[buf][r + 8][ks + lc + 4];
#pragma unroll
                for (int nt = 0; nt < 4; nt++)
                    mma_tf32(acc[mt][nt], a0, a1, a2, a3, bf[nt][0], bf[nt][1]);
            }
        }
        if (more) {
            int nb = buf ^ 1;
            uint32_t ua[8], ub[8];
#pragma unroll
            for (int j = 0; j < 8; j++) { ua[j] = f2tf32(ra[j]); ub[j] = f2tf32(rb[j]); }
            *(uint4*)&As[nb][rr][kc]     = make_uint4(ua[0], ua[1], ua[2], ua[3]);
            *(uint4*)&As[nb][rr][kc + 4] = make_uint4(ua[4], ua[5], ua[6], ua[7]);
            *(uint4*)&Bs[nb][rr][kc]     = make_uint4(ub[0], ub[1], ub[2], ub[3]);
            *(uint4*)&Bs[nb][rr][kc + 4] = make_uint4(ub[4], ub[5], ub[6], ub[7]);
            __syncthreads();
            buf = nb;
        }
    }

    bool interior = (nBase + 128) <= NVALID;
#pragma unroll
    for (int mt = 0; mt < 4; mt++) {
        int r1 = mBase + mW + mt * 16 + lr;
        int r2 = r1 + 8;
#pragma unroll
        for (int nt = 0; nt < 4; nt++) {
            int cb = nBase + nW + nt * 8 + lc * 2;
            if (interior) {
                if (r1 < M) {
                    size_t off = (size_t)g * sC + (size_t)r1 * ldC + cb;
                    *(float2*)(C + off) = make_float2(__expf(30.0f * acc[mt][nt][0]),
                                                      __expf(30.0f * acc[mt][nt][1]));
                }
                if (r2 < M) {
                    size_t off = (size_t)g * sC + (size_t)r2 * ldC + cb;
                    *(float2*)(C + off) = make_float2(__expf(30.0f * acc[mt][nt][2]),
                                                      __expf(30.0f * acc[mt][nt][3]));
                }
            } else {
#pragma unroll
                for (int e = 0; e < 2; e++) {
                    int n = cb + e;
                    if (n >= ldC) continue;
                    if (r1 < M)
                        C[(size_t)g * sC + (size_t)r1 * ldC + n] =
                            (n < NVALID) ? __expf(30.0f * acc[mt][nt][e]) : 0.0f;
                    if (r2 < M)
                        C[(size_t)g * sC + (size_t)r2 * ldC + n] =
                            (n < NVALID) ? __expf(30.0f * acc[mt][nt][2 + e]) : 0.0f;
                }
            }
        }
    }
}

// ============ tf32 value GEMM with fused rowsum/mask + consumer scales ======
// VSCALE: V row k scaled by VSCALE[gk*3 + k/484] (cross: V = x1e groups).
// CINSC:  Cin scaled by CINSC[g] in epilogue (cross: Cin = dx1).
__global__ void __launch_bounds__(256, 2)
tf32_value_kernel(const float* __restrict__ P, const float* __restrict__ V,
                  const float* __restrict__ Cin, float* __restrict__ C,
                  const float* __restrict__ LAB, float* __restrict__ MASKOUT,
                  const float* __restrict__ VSCALE, const float* __restrict__ CINSC,
                  int M, int Kpad, int KB, int ldA,
                  size_t sA, size_t sB, size_t sC, int gkMod) {
    __shared__ __align__(16) uint32_t As[2][128][20];
    __shared__ __align__(16) uint32_t Bs[2][16][136];
    __shared__ float rs_s[128][2];
    __shared__ float rm_s[128][2];
    int g = blockIdx.z;
    int gk = gkMod ? (g & 15) : g;
    const float* Pg = P + (size_t)g * sA;
    const float* Vg = V + (size_t)gk * sB;
    const float* labRow = LAB ? (LAB + (size_t)gk * KB) : nullptr;
    int mBase = blockIdx.y * 128, nBase = blockIdx.x * 128;
    int t = threadIdx.x, lane = t & 31, warp = t >> 5;
    int mW = (warp >> 2) * 64, nW = (warp & 3) * 32;

    int am = t >> 1, ak = (t & 1) * 8;
    bool avalid = (mBase + am) < M;
    const float* aPtr = Pg + (size_t)(mBase + am) * ldA + ak;
    int bk2 = t >> 4, bnq = (t & 15) * 8;
    const float* bPtr = Vg + (size_t)bk2 * 512 + nBase + bnq;

    float psum = 0.0f, pmask = 0.0f;
    float ra[8], rb[8];
    ld8(aPtr, avalid, ra);
#pragma unroll
    for (int j = 0; j < 8; j++) psum += ra[j];
    if (labRow) {
#pragma unroll
        for (int j = 0; j < 8; j++) {
            int k = ak + j;
            if (k < KB) pmask += ra[j] * labRow[k];
        }
    }
    {
        bool bv = bk2 < KB;
        ld8(bPtr, bv, rb);
        if (bv) {
            float sc = 1.0f;
            if (labRow) sc = labRow[bk2];
            if (VSCALE) sc *= VSCALE[gk * 3 + bk2 / 484];
            if (labRow || VSCALE) {
#pragma unroll
                for (int j = 0; j < 8; j++) rb[j] *= sc;
            }
        }
    }
    {
        uint32_t ua[8], ub[8];
#pragma unroll
        for (int j = 0; j < 8; j++) { ua[j] = f2tf32(ra[j]); ub[j] = f2tf32(rb[j]); }
        *(uint4*)&As[0][am][ak]     = make_uint4(ua[0], ua[1], ua[2], ua[3]);
        *(uint4*)&As[0][am][ak + 4] = make_uint4(ua[4], ua[5], ua[6], ua[7]);
        *(uint4*)&Bs[0][bk2][bnq]     = make_uint4(ub[0], ub[1], ub[2], ub[3]);
        *(uint4*)&Bs[0][bk2][bnq + 4] = make_uint4(ub[4], ub[5], ub[6], ub[7]);
    }
    __syncthreads();

    float acc[4][4][4];
#pragma unroll
    for (int i = 0; i < 4; i++)
#pragma unroll
        for (int j = 0; j < 4; j++)
#pragma unroll
            for (int q = 0; q < 4; q++) acc[i][j][q] = 0.0f;

    int buf = 0;
    int lr = lane >> 2, lc = lane & 3;

    for (int k0 = 0; k0 < Kpad; k0 += 16) {
        int kn = k0 + 16;
        bool more = kn < Kpad;
        if (more) {
            ld8(aPtr + kn, avalid, ra);
#pragma unroll
            for (int j = 0; j < 8; j++) psum += ra[j];
            if (labRow) {
#pragma unroll
                for (int j = 0; j < 8; j++) {
                    int k = kn + ak + j;
                    if (k < KB) pmask += ra[j] * labRow[k];
                }
            }
            int krow = kn + bk2;
            bool bv = krow < KB;
            ld8(bPtr + (size_t)kn * 512, bv, rb);
            if (bv) {
                float sc = 1.0f;
                if (labRow) sc = labRow[krow];
                if (VSCALE) sc *= VSCALE[gk * 3 + krow / 484];
                if (labRow || VSCALE) {
#pragma unroll
                    for (int j = 0; j < 8; j++) rb[j] *= sc;
                }
            }
        }
#pragma unroll
        for (int ks = 0; ks < 16; ks += 8) {
            uint32_t bf[4][2];
#pragma unroll
            for (int nt = 0; nt < 4; nt++) {
                int cc = nW + nt * 8 + lr;
                bf[nt][0] = Bs[buf][ks + lc][cc];
                bf[nt][1] = Bs[buf][ks + lc + 4][cc];
            }
#pragma unroll
            for (int mt = 0; mt < 4; mt++) {
                int r = mW + mt * 16 + lr;
                uint32_t a0 = As[buf][r][ks + lc];
                uint32_t a1 = As[buf][r + 8][ks + lc];
                uint32_t a2 = As[buf][r][ks + lc + 4];
                uint32_t a3 = As[buf][r + 8][ks + lc + 4];
#pragma unroll
                for (int nt = 0; nt < 4; nt++)
                    mma_tf32(acc[mt][nt], a0, a1, a2, a3, bf[nt][0], bf[nt][1]);
            }
        }
        if (more) {
            int nb = buf ^ 1;
            uint32_t ua[8], ub[8];
#pragma unroll
            for (int j = 0; j < 8; j++) { ua[j] = f2tf32(ra[j]); ub[j] = f2tf32(rb[j]); }
            *(uint4*)&As[nb][am][ak]     = make_uint4(ua[0], ua[1], ua[2], ua[3]);
            *(uint4*)&As[nb][am][ak + 4] = make_uint4(ua[4], ua[5], ua[6], ua[7]);
            *(uint4*)&Bs[nb][bk2][bnq]     = make_uint4(ub[0], ub[1], ub[2], ub[3]);
            *(uint4*)&Bs[nb][bk2][bnq + 4] = make_uint4(ub[4], ub[5], ub[6], ub[7]);
            __syncthreads();
            buf = nb;
        }
    }

    rs_s[am][t & 1] = psum;
    rm_s[am][t & 1] = pmask;
    __syncthreads();

    if (labRow && MASKOUT && blockIdx.x == 0 && t < 128) {
        int row = mBase + t;
        if (row < M) {
            float s = rs_s[t][0] + rs_s[t][1];
            MASKOUT[(size_t)g * M + row] = (rm_s[t][0] + rm_s[t][1]) / s;
        }
    }

    float csc = CINSC ? CINSC[g] : 1.0f;
#pragma unroll
    for (int mt = 0; mt < 4; mt++) {
        int l1 = mW + mt * 16 + lr, l2 = l1 + 8;
        int r1 = mBase + l1, r2 = mBase + l2;
        float rs1 = (r1 < M) ? 1.0f / (rs_s[l1][0] + rs_s[l1][1]) : 0.0f;
        float rs2 = (r2 < M) ? 1.0f / (rs_s[l2][0] + rs_s[l2][1]) : 0.0f;
#pragma unroll
        for (int nt = 0; nt < 4; nt++) {
            int cb = nBase + nW + nt * 8 + lc * 2;
            if (r1 < M) {
                size_t off = (size_t)g * sC + (size_t)r1 * 512 + cb;
                float2 ci = *(const float2*)(Cin + off);
                *(float2*)(C + off) = make_float2(rs1 * acc[mt][nt][0] + ci.x * csc,
                                                  rs1 * acc[mt][nt][1] + ci.y * csc);
            }
            if (r2 < M) {
                size_t off = (size_t)g * sC + (size_t)r2 * 512 + cb;
                float2 ci = *(const float2*)(Cin + off);
                *(float2*)(C + off) = make_float2(rs2 * acc[mt][nt][2] + ci.x * csc,
                                                  rs2 * acc[mt][nt][3] + ci.y * csc);
            }
        }
    }
}

// ================= small kernels =================
__global__ void pe_kernel(float* __restrict__ pe) {
    int idx = blockIdx.x * 256 + threadIdx.x;
    if (idx >= HW * DD) return;
    int p = idx >> 9, c = idx & 511;
    float pos = (float)(p + 1);
    int j = c & 255;
    float f = powf(10000.0f, -(float)j * (1.0f / 256.0f));
    float a = pos * f;
    pe[idx] = (c < 256) ? sinf(a) : cosf(a);
}

__global__ void label_kernel(const float* __restrict__ lab, float* __restrict__ out) {
    int idx = blockIdx.x * 256 + threadIdx.x;
    if (idx >= 3 * BB * HW) return;
    int p = idx % HW;
    int t = idx / HW;
    int b = t % BB;
    int ni = t / BB;
    out[(size_t)b * LE + ni * HW + p] = lab[idx];
}

__global__ void __launch_bounds__(256)
build_kernel(const float* __restrict__ fa, const float* __restrict__ fb,
             int split, const float* __restrict__ pe,
             float* __restrict__ xout, int mode) {
    int g = blockIdx.x;
    int img = g >> 4, b = g & 15;
    const float* f = (img < split) ? (fa + (size_t)img * BB * DD * HW)
                                   : (fb + (size_t)(img - split) * BB * DD * HW);
    int p0 = blockIdx.y * 32, c0 = blockIdx.z * 32;
    __shared__ float tl[32][33];
    int t = threadIdx.x;
    {
        int c = t >> 3, pg = t & 7;
        int p = p0 + pg * 4;
        if (p < HW) {
            float4 v = *(const float4*)(f + ((size_t)b * DD + c0 + c) * HW + p);
            tl[pg * 4 + 0][c] = v.x;
            tl[pg * 4 + 1][c] = v.y;
            tl[pg * 4 + 2][c] = v.z;
            tl[pg * 4 + 3][c] = v.w;
        }
    }
    __syncthreads();
    {
        int p = t >> 3, cg = t & 7;
        int gp = p0 + p;
        if (gp < HW) {
            int c = c0 + cg * 4;
            float4 pv = *(const float4*)(pe + (size_t)gp * DD + c);
            float4 o;
            o.x = tl[p][cg * 4 + 0] + pv.x * 1e-3f;
            o.y = tl[p][cg * 4 + 1] + pv.y * 1e-3f;
            o.z = tl[p][cg * 4 + 2] + pv.z * 1e-3f;
            o.w = tl[p][cg * 4 + 3] + pv.w * 1e-3f;
            size_t row = (mode == 0) ? ((size_t)b * LE + (size_t)img * HW + gp)
                                     : ((size_t)g * LDQ + gp);
            *(float4*)(xout + row * DD + c) = o;
        }
    }
}

// InstanceL2Norm partial sums (groups of 484 rows = GRP floats)
__global__ void inorm_part(const float* __restrict__ in, float* __restrict__ part) {
    int g = blockIdx.x, q = blockIdx.y, t = threadIdx.x;
    const float4* ip = (const float4*)(in + (size_t)g * GRP) + (size_t)q * QF4;
    float ss = 0.0f;
    for (int i = t; i < QF4; i += 256) {
        float4 v = ip[i];
        ss += v.x * v.x + v.y * v.y + v.z * v.z + v.w * v.w;
    }
    __shared__ float red[8];
#pragma unroll
    for (int m = 16; m; m >>= 1) ss += __shfl_xor_sync(0xffffffffu, ss, m);
    if ((t & 31) == 0) red[t >> 5] = ss;
    __syncthreads();
    if (t == 0) {
        float s = 0.0f;
#pragma unroll
        for (int i = 0; i < 8; i++) s += red[i];
        part[g * 4 + q] = s;
    }
}

// group scale from 4 partials
__global__ void group_scale_kernel(const float* __restrict__ part,
                                   float* __restrict__ sc, int n) {
    int g = threadIdx.x;
    if (g >= n) return;
    float s = part[g * 4 + 0] + part[g * 4 + 1] + part[g * 4 + 2] + part[g * 4 + 3];
    sc[g] = NSCALE * sqrtf(DHWF / (s + IEPS));
}

// decoder 3-sum partials: u = (x*dsc)*mask, v = xp
__global__ void dec_part_kernel(const float* __restrict__ X, const float* __restrict__ XP,
                                const float* __restrict__ MASK,
                                const float* __restrict__ DSC,
                                float* __restrict__ part) {
    int g = blockIdx.x, q = blockIdx.y, t = threadIdx.x;
    const float4* x4 = (const float4*)(X + (size_t)g * GRP);
    const float4* p4 = (const float4*)(XP + (size_t)g * GRP);
    const float* mk = MASK + (size_t)g * LDQ;
    float ds = DSC[g];
    float s2 = 0.0f, s4 = 0.0f, cr = 0.0f;
    for (int i = t; i < QF4; i += 256) {
        int gi = q * QF4 + i;
        float m = mk[gi >> 7] * ds;
        float4 x = x4[gi];
        float4 v = p4[gi];
        float ux = x.x * m, uy = x.y * m, uz = x.z * m, uw = x.w * m;
        s2 += ux * ux + uy * uy + uz * uz + uw * uw;
        s4 += v.x * v.x + v.y * v.y + v.z * v.z + v.w * v.w;
        cr += ux * v.x + uy * v.y + uz * v.z + uw * v.w;
    }
    __shared__ float r2[8], r4[8], rc[8];
#pragma unroll
    for (int m = 16; m; m >>= 1) {
        s2 += __shfl_xor_sync(0xffffffffu, s2, m);
        s4 += __shfl_xor_sync(0xffffffffu, s4, m);
        cr += __shfl_xor_sync(0xffffffffu, cr, m);
    }
    if ((t & 31) == 0) { r2[t >> 5] = s2; r4[t >> 5] = s4; rc[t >> 5] = cr; }
    __syncthreads();
    if (t == 0) {
        float a = 0, b = 0, c = 0;
#pragma unroll
        for (int i = 0; i < 8; i++) { a += r2[i]; b += r4[i]; c += rc[i]; }
        part[(g * 4 + q) * 3 + 0] = a;
        part[(g * 4 + q) * 3 + 1] = b;
        part[(g * 4 + q) * 3 + 2] = c;
    }
}

__global__ void dec_scale_kernel(const float* __restrict__ part, float* __restrict__ SC) {
    int g = threadIdx.x;
    if (g >= 96) return;
    float a = 0, b = 0, c = 0;
#pragma unroll
    for (int q = 0; q < 4; q++) {
        a += part[(g * 4 + q) * 3 + 0];
        b += part[(g * 4 + q) * 3 + 1];
        c += part[(g * 4 + q) * 3 + 2];
    }
    float S2 = NSCALE * sqrtf(DHWF / (a + IEPS));
    float S4 = NSCALE * sqrtf(DHWF / (b + IEPS));
    float sso = S2 * S2 * a + 2.0f * S2 * S4 * c + S4 * S4 * b;
    float SO = NSCALE * sqrtf(DHWF / (sso + IEPS));
    SC[g * 4 + 0] = S2;
    SC[g * 4 + 1] = S4;
    SC[g * 4 + 2] = SO;
}

__global__ void final_kernel(const float* __restrict__ X, const float* __restrict__ XP,
                             const float* __restrict__ MASK, const float* __restrict__ SC,
                             const float* __restrict__ DSC, float* __restrict__ out) {
    int g = blockIdx.x;
    float S2 = SC[g * 4 + 0], S4 = SC[g * 4 + 1], SO = SC[g * 4 + 2];
    float ds = DSC[g];
    int p0 = blockIdx.y * 32, c0 = blockIdx.z * 32;
    __shared__ float tile[32][33];
    int tx = threadIdx.x, ty = threadIdx.y;
    size_t base = (size_t)g * GRP;
#pragma unroll
    for (int r = 0; r < 4; r++) {
        int p = p0 + ty + r * 8, c = c0 + tx;
        if (p < LDQ) {
            size_t idx = base + (size_t)p * 512 + c;
            float u = X[idx] * ds * MASK[(size_t)g * LDQ + p];
            tile[ty + r * 8][tx] = SO * (S2 * u + S4 * XP[idx]);
        }
    }
    __syncthreads();
#pragma unroll
    for (int r = 0; r < 4; r++) {
        int p = p0 + tx, c = c0 + ty + r * 8;
        if (p < LDQ) out[((size_t)g * 512 + c) * LDQ + p] = tile[tx][ty + r * 8];
    }
}

// ================= launcher =================
extern "C" void kernel_launch(void* const* d_in, const int* in_sizes, int n_in,
                              void* d_out, int out_size) {
    const float* train_feat  = (const float*)d_in[0];
    const float* test_feat   = (const float*)d_in[1];
    const float* train_label = (const float*)d_in[2];
    const float* wk_self     = (const float*)d_in[3];
    const float* bk_self     = (const float*)d_in[4];
    const float* wk_cross    = (const float*)d_in[5];
    const float* bk_cross    = (const float*)d_in[6];
    float* out = (float*)d_out;

    float* base = nullptr;
    cudaGetSymbolAddress((void**)&base, g_scratch);
    float* pe     = base + OFF_PE;
    float* label  = base + OFF_LABEL;
    float* xe     = base + OFF_XE;
    float* dx0    = base + OFF_DX0;
    float* pq     = base + OFF_PQ;
    float* dpq    = base + OFF_DPQ;
    float* x1e    = base + OFF_X1E;
    float* dx1    = base + OFF_DX1;
    float* pkc    = base + OFF_PKC;
    float* dpq2   = base + OFF_DPQ2;
    float* dxpt3  = base + OFF_DXPT3;
    float* dmask  = base + OFF_DMASK;
    float* dsc    = base + OFF_DSC;
    float* ipart  = base + OFF_IPART;
    float* dparti = base + OFF_DPARTI;
    float* dpart3 = base + OFF_DPART3;
    float* sc144  = base + OFF_SC144;
    float* probs  = base + OFF_PROBS;

    dim3 tb(32, 8);
    const int MALL = 16 * LE + 96 * LDQ;

    pe_kernel<<<(HW * DD + 255) / 256, 256>>>(pe);
    label_kernel<<<(3 * BB * HW + 255) / 256, 256>>>(train_label, label);

    build_kernel<<<dim3(48, 16, 16), 256>>>(train_feat, train_feat, 3, pe, xe, 0);
    build_kernel<<<dim3(96, 16, 16), 256>>>(train_feat, test_feat, 3, pe, dx0, 1);

    // merged self projection [xe|dx0] -> [pq|dpq]
    tf32_proj_kernel<<<dim3(1, (MALL + 127) / 128, 1), 256>>>(
        xe, wk_self, pq, bk_self, nullptr, MALL);

    // encoder
    tf32_logits_kernel<<<dim3(12, 12, 16), 256>>>(
        pq, pq, probs, LE, LE, 1456, LE,
        (size_t)LE * 128, (size_t)LE * 128, (size_t)LE * 1456, 0);
    tf32_value_kernel<<<dim3(4, 12, 16), 256>>>(
        probs, xe, xe, x1e, nullptr, nullptr, nullptr, nullptr,
        LE, 1456, LE, 1456,
        (size_t)LE * 1456, (size_t)LE * 512, (size_t)LE * 512, 0);
    inorm_part<<<dim3(48, 4), 256>>>(x1e, ipart);
    group_scale_kernel<<<1, 48>>>(ipart, sc144, 48);

    // decoder self
    tf32_logits_kernel<<<dim3(4, 4, 96), 256>>>(
        dpq, dpq, probs, LDQ, LDQ, 496, LDQ,
        (size_t)LDQ * 128, (size_t)LDQ * 128, (size_t)LDQ * 496, 0);
    tf32_value_kernel<<<dim3(4, 4, 96), 256>>>(
        probs, dx0, dx0, dx1, nullptr, nullptr, nullptr, nullptr,
        LDQ, 496, LDQ, 496,
        (size_t)LDQ * 496, (size_t)LDQ * 512, (size_t)LDQ * 512, 0);
    inorm_part<<<dim3(96, 4), 256>>>(dx1, dparti);
    group_scale_kernel<<<1, 96>>>(dparti, sc144 + 48, 96);

    // merged cross projection over scaled [x1e|dx1] -> [pkc|dpq2]
    tf32_proj_kernel<<<dim3(1, (MALL + 127) / 128, 1), 256>>>(
        x1e, wk_cross, pkc, bk_cross, sc144, MALL);

    // cross attention: V = x1e (group-scaled) * label, Cin = dx1 * dscale
    tf32_logits_kernel<<<dim3(12, 4, 96), 256>>>(
        dpq2, pkc, probs, LDQ, LE, 1456, LE,
        (size_t)LDQ * 128, (size_t)LE * 128, (size_t)LDQ * 1456, 1);
    tf32_value_kernel<<<dim3(4, 4, 96), 256>>>(
        probs, x1e, dx1, dxpt3, label, dmask, sc144, sc144 + 48,
        LDQ, 1456, LE, 1456,
        (size_t)LDQ * 1456, (size_t)LE * 512, (size_t)LDQ * 512, 1);

    dec_part_kernel<<<dim3(96, 4), 256>>>(dx1, dxpt3, dmask, sc144 + 48, dpart3);
    dec_scale_kernel<<<1, 96>>>(dpart3, dsc);
    final_kernel<<<dim3(96, 16, 16), tb>>>(dx1, dxpt3, dmask, dsc, sc144 + 48, out);
}

// round 17
// speedup vs baseline: 1.1787x; 1.1787x over previous
#include <cuda_runtime.h>
#include <math.h>
#include <stdint.h>

#define BB 16
#define DD 512
#define HW 484
#define LE 1452
#define LDQ 484
#define NSCALE 0.011048543456039806f
#define DHWF 247808.0f
#define IEPS 1e-5f
#define GRP 247808
#define QF4 15488

#define SZ_PE     ((size_t)HW*DD)
#define SZ_LABEL  ((size_t)BB*LE)
#define SZ_XE     ((size_t)BB*LE*DD)
#define SZ_DX0    ((size_t)96*LDQ*DD)
#define SZ_PQ     ((size_t)BB*LE*128)
#define SZ_DPQ    ((size_t)96*LDQ*128)
#define SZ_DMASK  ((size_t)96*LDQ)
#define SZ_PROBS  ((size_t)96*LDQ*1456)

#define OFF_PE    ((size_t)0)
#define OFF_LABEL (OFF_PE + SZ_PE)
#define OFF_XE    (OFF_LABEL + SZ_LABEL)
#define OFF_DX0   (OFF_XE + SZ_XE)
#define OFF_PQ    (OFF_DX0 + SZ_DX0)
#define OFF_DPQ   (OFF_PQ + SZ_PQ)
#define OFF_MEM   (OFF_DPQ + SZ_DPQ)
#define OFF_DX    (OFF_MEM + SZ_XE)
#define OFF_PKC   (OFF_DX + SZ_DX0)
#define OFF_DPQ2  (OFF_PKC + SZ_PQ)
#define OFF_X1E   (OFF_DPQ2 + SZ_DPQ)
#define OFF_DX1   (OFF_X1E + SZ_XE)
#define OFF_DXPT3 (OFF_DX1 + SZ_DX0)
#define OFF_DMASK (OFF_DXPT3 + SZ_DX0)
#define OFF_DSC   (OFF_DMASK + SZ_DMASK)
#define OFF_IPART (OFF_DSC + 96*4)
#define OFF_DPART (OFF_IPART + 96*4)
#define OFF_PROBS (OFF_DPART + 96*4*3)
#define SCRATCH_TOTAL (OFF_PROBS + SZ_PROBS)

__device__ __align__(16) float g_scratch[SCRATCH_TOTAL];

__device__ __forceinline__ uint32_t f2tf32(float f) {
    uint32_t u;
    asm("cvt.rna.tf32.f32 %0, %1;" : "=r"(u) : "f"(f));
    return u;
}
__device__ __forceinline__ void mma_tf32(float* c, uint32_t a0, uint32_t a1,
                                         uint32_t a2, uint32_t a3,
                                         uint32_t b0, uint32_t b1) {
    asm volatile("mma.sync.aligned.m16n8k8.row.col.f32.tf32.tf32.f32 "
                 "{%0,%1,%2,%3}, {%4,%5,%6,%7}, {%8,%9}, {%0,%1,%2,%3};"
                 : "+f"(c[0]), "+f"(c[1]), "+f"(c[2]), "+f"(c[3])
                 : "r"(a0), "r"(a1), "r"(a2), "r"(a3), "r"(b0), "r"(b1));
}
__device__ __forceinline__ void ld8(const float* p, bool valid, float* r) {
    if (valid) {
        float4 v0 = *(const float4*)p;
        float4 v1 = *(const float4*)(p + 4);
        r[0] = v0.x; r[1] = v0.y; r[2] = v0.z; r[3] = v0.w;
        r[4] = v1.x; r[5] = v1.y; r[6] = v1.z; r[7] = v1.w;
    } else {
#pragma unroll
        for (int j = 0; j < 8; j++) r[j] = 0.0f;
    }
}

// ============ tf32 projection GEMM (NT, K=512, N=128) + bias + L2norm ======
__global__ void __launch_bounds__(256, 2)
tf32_proj_kernel(const float* __restrict__ A, const float* __restrict__ W,
                 float* __restrict__ C, const float* __restrict__ BIAS, int M) {
    __shared__ __align__(16) uint32_t As[2][128][20];
    __shared__ __align__(16) uint32_t Bs[2][128][20];
    __shared__ float ssq[128][4];
    int mBase = blockIdx.y * 128;
    int t = threadIdx.x, lane = t & 31, warp = t >> 5;
    int mW = (warp >> 2) * 64, nW = (warp & 3) * 32;

    int rr = t >> 1, kc = (t & 1) * 8;
    bool avalid = (mBase + rr) < M;
    const float* aPtr = A + (size_t)(mBase + rr) * 512 + kc;
    const float* bPtr = W + (size_t)rr * 512 + kc;

    float ra[8], rb[8];
    ld8(aPtr, avalid, ra);
    ld8(bPtr, true, rb);
    {
        uint32_t ua[8], ub[8];
#pragma unroll
        for (int j = 0; j < 8; j++) { ua[j] = f2tf32(ra[j]); ub[j] = f2tf32(rb[j]); }
        *(uint4*)&As[0][rr][kc]     = make_uint4(ua[0], ua[1], ua[2], ua[3]);
        *(uint4*)&As[0][rr][kc + 4] = make_uint4(ua[4], ua[5], ua[6], ua[7]);
        *(uint4*)&Bs[0][rr][kc]     = make_uint4(ub[0], ub[1], ub[2], ub[3]);
        *(uint4*)&Bs[0][rr][kc + 4] = make_uint4(ub[4], ub[5], ub[6], ub[7]);
    }
    __syncthreads();

    float acc[4][4][4];
#pragma unroll
    for (int i = 0; i < 4; i++)
#pragma unroll
        for (int j = 0; j < 4; j++)
#pragma unroll
            for (int q = 0; q < 4; q++) acc[i][j][q] = 0.0f;

    int buf = 0;
    int lr = lane >> 2, lc = lane & 3;

    for (int k0 = 0; k0 < 512; k0 += 16) {
        int kn = k0 + 16;
        bool more = kn < 512;
        if (more) {
            ld8(aPtr + kn, avalid, ra);
            ld8(bPtr + kn, true, rb);
        }
#pragma unroll
        for (int ks = 0; ks < 16; ks += 8) {
            uint32_t bf[4][2];
#pragma unroll
            for (int nt = 0; nt < 4; nt++) {
                int nn = nW + nt * 8 + lr;
                bf[nt][0] = Bs[buf][nn][ks + lc];
                bf[nt][1] = Bs[buf][nn][ks + lc + 4];
            }
#pragma unroll
            for (int mt = 0; mt < 4; mt++) {
                int r = mW + mt * 16 + lr;
                uint32_t a0 = As[buf][r][ks + lc];
                uint32_t a1 = As[buf][r + 8][ks + lc];
                uint32_t a2 = As[buf][r][ks + lc + 4];
                uint32_t a3 = As[buf][r + 8][ks + lc + 4];
#pragma unroll
                for (int nt = 0; nt < 4; nt++)
                    mma_tf32(acc[mt][nt], a0, a1, a2, a3, bf[nt][0], bf[nt][1]);
            }
        }
        if (more) {
            int nb = buf ^ 1;
            uint32_t ua[8], ub[8];
#pragma unroll
            for (int j = 0; j < 8; j++) { ua[j] = f2tf32(ra[j]); ub[j] = f2tf32(rb[j]); }
            *(uint4*)&As[nb][rr][kc]     = make_uint4(ua[0], ua[1], ua[2], ua[3]);
            *(uint4*)&As[nb][rr][kc + 4] = make_uint4(ua[4], ua[5], ua[6], ua[7]);
            *(uint4*)&Bs[nb][rr][kc]     = make_uint4(ub[0], ub[1], ub[2], ub[3]);
            *(uint4*)&Bs[nb][rr][kc + 4] = make_uint4(ub[4], ub[5], ub[6], ub[7]);
            __syncthreads();
            buf = nb;
        }
    }

    float bv[4][2];
#pragma unroll
    for (int nt = 0; nt < 4; nt++) {
        bv[nt][0] = BIAS[nW + nt * 8 + lc * 2];
        bv[nt][1] = BIAS[nW + nt * 8 + lc * 2 + 1];
    }
#pragma unroll
    for (int mt = 0; mt < 4; mt++) {
        float p1 = 0.0f, p2 = 0.0f;
#pragma unroll
        for (int nt = 0; nt < 4; nt++) {
            acc[mt][nt][0] += bv[nt][0];
            acc[mt][nt][1] += bv[nt][1];
            acc[mt][nt][2] += bv[nt][0];
            acc[mt][nt][3] += bv[nt][1];
            p1 += acc[mt][nt][0] * acc[mt][nt][0] + acc[mt][nt][1] * acc[mt][nt][1];
            p2 += acc[mt][nt][2] * acc[mt][nt][2] + acc[mt][nt][3] * acc[mt][nt][3];
        }
        p1 += __shfl_xor_sync(0xffffffffu, p1, 1);
        p1 += __shfl_xor_sync(0xffffffffu, p1, 2);
        p2 += __shfl_xor_sync(0xffffffffu, p2, 1);
        p2 += __shfl_xor_sync(0xffffffffu, p2, 2);
        if (lc == 0) {
            ssq[mW + mt * 16 + lr][warp & 3] = p1;
            ssq[mW + mt * 16 + lr + 8][warp & 3] = p2;
        }
    }
    __syncthreads();
#pragma unroll
    for (int mt = 0; mt < 4; mt++) {
        int l1 = mW + mt * 16 + lr, l2 = l1 + 8;
        float s1 = ssq[l1][0] + ssq[l1][1] + ssq[l1][2] + ssq[l1][3];
        float s2 = ssq[l2][0] + ssq[l2][1] + ssq[l2][2] + ssq[l2][3];
        float rn1 = 1.0f / fmaxf(sqrtf(s1), 1e-12f);
        float rn2 = 1.0f / fmaxf(sqrtf(s2), 1e-12f);
        int r1 = mBase + l1, r2 = mBase + l2;
#pragma unroll
        for (int nt = 0; nt < 4; nt++) {
            int cb = nW + nt * 8 + lc * 2;
            if (r1 < M)
                *(float2*)(C + (size_t)r1 * 128 + cb) =
                    make_float2(acc[mt][nt][0] * rn1, acc[mt][nt][1] * rn1);
            if (r2 < M)
                *(float2*)(C + (size_t)r2 * 128 + cb) =
                    make_float2(acc[mt][nt][2] * rn2, acc[mt][nt][3] * rn2);
        }
    }
}

// ============ tf32 logits GEMM (NT) + exp epilogue ============
__global__ void __launch_bounds__(256, 2)
tf32_logits_kernel(const float* __restrict__ PQ, const float* __restrict__ PK,
                   float* __restrict__ C, int M, int N, int ldC, int NVALID,
                   size_t sA, size_t sB, size_t sC, int gkMod) {
    __shared__ __align__(16) uint32_t As[2][128][20];
    __shared__ __align__(16) uint32_t Bs[2][128][20];
    int g = blockIdx.z;
    int gk = gkMod ? (g & 15) : g;
    const float* Ag = PQ + (size_t)g * sA;
    const float* Bg = PK + (size_t)gk * sB;
    int mBase = blockIdx.y * 128, nBase = blockIdx.x * 128;
    int t = threadIdx.x, lane = t & 31, warp = t >> 5;
    int mW = (warp >> 2) * 64, nW = (warp & 3) * 32;

    int rr = t >> 1, kc = (t & 1) * 8;
    bool avalid = (mBase + rr) < M;
    bool bvalid = (nBase + rr) < N;
    const float* aPtr = Ag + (size_t)(mBase + rr) * 128 + kc;
    const float* bPtr = Bg + (size_t)(nBase + rr) * 128 + kc;

    float ra[8], rb[8];
    ld8(aPtr, avalid, ra);
    ld8(bPtr, bvalid, rb);
    {
        uint32_t ua[8], ub[8];
#pragma unroll
        for (int j = 0; j < 8; j++) { ua[j] = f2tf32(ra[j]); ub[j] = f2tf32(rb[j]); }
        *(uint4*)&As[0][rr][kc]     = make_uint4(ua[0], ua[1], ua[2], ua[3]);
        *(uint4*)&As[0][rr][kc + 4] = make_uint4(ua[4], ua[5], ua[6], ua[7]);
        *(uint4*)&Bs[0][rr][kc]     = make_uint4(ub[0], ub[1], ub[2], ub[3]);
        *(uint4*)&Bs[0][rr][kc + 4] = make_uint4(ub[4], ub[5], ub[6], ub[7]);
    }
    __syncthreads();

    float acc[4][4][4];
#pragma unroll
    for (int i = 0; i < 4; i++)
#pragma unroll
        for (int j = 0; j < 4; j++)
#pragma unroll
            for (int q = 0; q < 4; q++) acc[i][j][q] = 0.0f;

    int buf = 0;
    int lr = lane >> 2, lc = lane & 3;

    for (int k0 = 0; k0 < 128; k0 += 16) {
        int kn = k0 + 16;
        bool more = kn < 128;
        if (more) {
            ld8(aPtr + kn, avalid, ra);
            ld8(bPtr + kn, bvalid, rb);
        }
#pragma unroll
        for (int ks = 0; ks < 16; ks += 8) {
            uint32_t bf[4][2];
#pragma unroll
            for (int nt = 0; nt < 4; nt++) {
                int nn = nW + nt * 8 + lr;
                bf[nt][0] = Bs[buf][nn][ks + lc];
                bf[nt][1] = Bs[buf][nn][ks + lc + 4];
            }
#pragma unroll
            for (int mt = 0; mt < 4; mt++) {
                int r = mW + mt * 16 + lr;
                uint32_t a0 = As[buf][r][ks + lc];
                uint32_t a1 = As[buf][r + 8][ks + lc];
                uint32_t a2 = As[buf][r][ks + lc + 4];
                uint32_t a3 = As[buf][r + 8][ks + lc + 4];
#pragma unroll
                for (int nt = 0; nt < 4; nt++)
                    mma_tf32(acc[mt][nt], a0, a1, a2, a3, bf[nt][0], bf[nt][1]);
            }
        }
        if (more) {
            int nb = buf ^ 1;
            uint32_t ua[8], ub[8];
#pragma unroll
            for (int j = 0; j < 8; j++) { ua[j] = f2tf32(ra[j]); ub[j] = f2tf32(rb[j]); }
            *(uint4*)&As[nb][rr][kc]     = make_uint4(ua[0], ua[1], ua[2], ua[3]);
            *(uint4*)&As[nb][rr][kc + 4] = make_uint4(ua[4], ua[5], ua[6], ua[7]);
            *(uint4*)&Bs[nb][rr][kc]     = make_uint4(ub[0], ub[1], ub[2], ub[3]);
            *(uint4*)&Bs[nb][rr][kc + 4] = make_uint4(ub[4], ub[5], ub[6], ub[7]);
            __syncthreads();
            buf = nb;
        }
    }

    bool interior = (nBase + 128) <= NVALID;
#pragma unroll
    for (int mt = 0; mt < 4; mt++) {
        int r1 = mBase + mW + mt * 16 + lr;
        int r2 = r1 + 8;
#pragma unroll
        for (int nt = 0; nt < 4; nt++) {
            int cb = nBase + nW + nt * 8 + lc * 2;
            if (interior) {
                if (r1 < M) {
                    size_t off = (size_t)g * sC + (size_t)r1 * ldC + cb;
                    *(float2*)(C + off) = make_float2(__expf(30.0f * acc[mt][nt][0]),
                                                      __expf(30.0f * acc[mt][nt][1]));
                }
                if (r2 < M) {
                    size_t off = (size_t)g * sC + (size_t)r2 * ldC + cb;
                    *(float2*)(C + off) = make_float2(__expf(30.0f * acc[mt][nt][2]),
                                                      __expf(30.0f * acc[mt][nt][3]));
                }
            } else {
#pragma unroll
                for (int e = 0; e < 2; e++) {
                    int n = cb + e;
                    if (n >= ldC) continue;
                    if (r1 < M)
                        C[(size_t)g * sC + (size_t)r1 * ldC + n] =
                            (n < NVALID) ? __expf(30.0f * acc[mt][nt][e]) : 0.0f;
                    if (r2 < M)
                        C[(size_t)g * sC + (size_t)r2 * ldC + n] =
                            (n < NVALID) ? __expf(30.0f * acc[mt][nt][2 + e]) : 0.0f;
                }
            }
        }
    }
}

// ============ tf32 value GEMM with fused rowsum (and mask) ============
__global__ void __launch_bounds__(256, 2)
tf32_value_kernel(const float* __restrict__ P, const float* __restrict__ V,
                  const float* __restrict__ Cin, float* __restrict__ C,
                  const float* __restrict__ LAB, float* __restrict__ MASKOUT,
                  int M, int Kpad, int KB, int ldA,
                  size_t sA, size_t sB, size_t sC, int gkMod) {
    __shared__ __align__(16) uint32_t As[2][128][20];
    __shared__ __align__(16) uint32_t Bs[2][16][136];
    __shared__ float rs_s[128][2];
    __shared__ float rm_s[128][2];
    int g = blockIdx.z;
    int gk = gkMod ? (g & 15) : g;
    const float* Pg = P + (size_t)g * sA;
    const float* Vg = V + (size_t)gk * sB;
    const float* labRow = LAB ? (LAB + (size_t)gk * KB) : nullptr;
    int mBase = blockIdx.y * 128, nBase = blockIdx.x * 128;
    int t = threadIdx.x, lane = t & 31, warp = t >> 5;
    int mW = (warp >> 2) * 64, nW = (warp & 3) * 32;

    int am = t >> 1, ak = (t & 1) * 8;
    bool avalid = (mBase + am) < M;
    const float* aPtr = Pg + (size_t)(mBase + am) * ldA + ak;
    int bk2 = t >> 4, bnq = (t & 15) * 8;
    const float* bPtr = Vg + (size_t)bk2 * 512 + nBase + bnq;

    float psum = 0.0f, pmask = 0.0f;
    float ra[8], rb[8];
    ld8(aPtr, avalid, ra);
#pragma unroll
    for (int j = 0; j < 8; j++) psum += ra[j];
    if (labRow) {
#pragma unroll
        for (int j = 0; j < 8; j++) {
            int k = ak + j;
            if (k < KB) pmask += ra[j] * labRow[k];
        }
    }
    {
        bool bv = bk2 < KB;
        ld8(bPtr, bv, rb);
        if (labRow && bv) {
            float lb = labRow[bk2];
#pragma unroll
            for (int j = 0; j < 8; j++) rb[j] *= lb;
        }
    }
    {
        uint32_t ua[8], ub[8];
#pragma unroll
        for (int j = 0; j < 8; j++) { ua[j] = f2tf32(ra[j]); ub[j] = f2tf32(rb[j]); }
        *(uint4*)&As[0][am][ak]     = make_uint4(ua[0], ua[1], ua[2], ua[3]);
        *(uint4*)&As[0][am][ak + 4] = make_uint4(ua[4], ua[5], ua[6], ua[7]);
        *(uint4*)&Bs[0][bk2][bnq]     = make_uint4(ub[0], ub[1], ub[2], ub[3]);
        *(uint4*)&Bs[0][bk2][bnq + 4] = make_uint4(ub[4], ub[5], ub[6], ub[7]);
    }
    __syncthreads();

    float acc[4][4][4];
#pragma unroll
    for (int i = 0; i < 4; i++)
#pragma unroll
        for (int j = 0; j < 4; j++)
#pragma unroll
            for (int q = 0; q < 4; q++) acc[i][j][q] = 0.0f;

    int buf = 0;
    int lr = lane >> 2, lc = lane & 3;

    for (int k0 = 0; k0 < Kpad; k0 += 16) {
        int kn = k0 + 16;
        bool more = kn < Kpad;
        if (more) {
            ld8(aPtr + kn, avalid, ra);
#pragma unroll
            for (int j = 0; j < 8; j++) psum += ra[j];
            if (labRow) {
#pragma unroll
                for (int j = 0; j < 8; j++) {
                    int k = kn + ak + j;
                    if (k < KB) pmask += ra[j] * labRow[k];
                }
            }
            bool bv = (kn + bk2) < KB;
            ld8(bPtr + (size_t)kn * 512, bv, rb);
            if (labRow && bv) {
                float lb = labRow[kn + bk2];
#pragma unroll
                for (int j = 0; j < 8; j++) rb[j] *= lb;
            }
        }
#pragma unroll
        for (int ks = 0; ks < 16; ks += 8) {
            uint32_t bf[4][2];
#pragma unroll
            for (int nt = 0; nt < 4; nt++) {
                int cc = nW + nt * 8 + lr;
                bf[nt][0] = Bs[buf][ks + lc][cc];
                bf[nt][1] = Bs[buf][ks + lc + 4][cc];
            }
#pragma unroll
            for (int mt = 0; mt < 4; mt++) {
                int r = mW + mt * 16 + lr;
                uint32_t a0 = As[buf][r][ks + lc];
                uint32_t a1 = As[buf][r + 8][ks + lc];
                uint32_t a2 = As[buf][r][ks + lc + 4];
                uint32_t a3 = As[buf][r + 8][ks + lc + 4];
#pragma unroll
                for (int nt = 0; nt < 4; nt++)
                    mma_tf32(acc[mt][nt], a0, a1, a2, a3, bf[nt][0], bf[nt][1]);
            }
        }
        if (more) {
            int nb = buf ^ 1;
            uint32_t ua[8], ub[8];
#pragma unroll
            for (int j = 0; j < 8; j++) { ua[j] = f2tf32(ra[j]); ub[j] = f2tf32(rb[j]); }
            *(uint4*)&As[nb][am][ak]     = make_uint4(ua[0], ua[1], ua[2], ua[3]);
            *(uint4*)&As[nb][am][ak + 4] = make_uint4(ua[4], ua[5], ua[6], ua[7]);
            *(uint4*)&Bs[nb][bk2][bnq]     = make_uint4(ub[0], ub[1], ub[2], ub[3]);
            *(uint4*)&Bs[nb][bk2][bnq + 4] = make_uint4(ub[4], ub[5], ub[6], ub[7]);
            __syncthreads();
            buf = nb;
        }
    }

    rs_s[am][t & 1] = psum;
    rm_s[am][t & 1] = pmask;
    __syncthreads();

    if (labRow && MASKOUT && blockIdx.x == 0 && t < 128) {
        int row = mBase + t;
        if (row < M) {
            float s = rs_s[t][0] + rs_s[t][1];
            MASKOUT[(size_t)g * M + row] = (rm_s[t][0] + rm_s[t][1]) / s;
        }
    }

#pragma unroll
    for (int mt = 0; mt < 4; mt++) {
        int l1 = mW + mt * 16 + lr, l2 = l1 + 8;
        int r1 = mBase + l1, r2 = mBase + l2;
        float rs1 = (r1 < M) ? 1.0f / (rs_s[l1][0] + rs_s[l1][1]) : 0.0f;
        float rs2 = (r2 < M) ? 1.0f / (rs_s[l2][0] + rs_s[l2][1]) : 0.0f;
#pragma unroll
        for (int nt = 0; nt < 4; nt++) {
            int cb = nBase + nW + nt * 8 + lc * 2;
            if (r1 < M) {
                size_t off = (size_t)g * sC + (size_t)r1 * 512 + cb;
                float2 ci = *(const float2*)(Cin + off);
                *(float2*)(C + off) = make_float2(rs1 * acc[mt][nt][0] + ci.x,
                                                  rs1 * acc[mt][nt][1] + ci.y);
            }
            if (r2 < M) {
                size_t off = (size_t)g * sC + (size_t)r2 * 512 + cb;
                float2 ci = *(const float2*)(Cin + off);
                *(float2*)(C + off) = make_float2(rs2 * acc[mt][nt][2] + ci.x,
                                                  rs2 * acc[mt][nt][3] + ci.y);
            }
        }
    }
}

// ================= small kernels =================
__global__ void pe_kernel(float* __restrict__ pe) {
    int idx = blockIdx.x * 256 + threadIdx.x;
    if (idx >= HW * DD) return;
    int p = idx >> 9, c = idx & 511;
    float pos = (float)(p + 1);
    int j = c & 255;
    float f = powf(10000.0f, -(float)j * (1.0f / 256.0f));
    float a = pos * f;
    pe[idx] = (c < 256) ? sinf(a) : cosf(a);
}

__global__ void label_kernel(const float* __restrict__ lab, float* __restrict__ out) {
    int idx = blockIdx.x * 256 + threadIdx.x;
    if (idx >= 3 * BB * HW) return;
    int p = idx % HW;
    int t = idx / HW;
    int b = t % BB;
    int ni = t / BB;
    out[(size_t)b * LE + ni * HW + p] = lab[idx];
}

__global__ void __launch_bounds__(256)
build_kernel(const float* __restrict__ fa, const float* __restrict__ fb,
             int split, const float* __restrict__ pe,
             float* __restrict__ xout, int mode) {
    int g = blockIdx.x;
    int img = g >> 4, b = g & 15;
    const float* f = (img < split) ? (fa + (size_t)img * BB * DD * HW)
                                   : (fb + (size_t)(img - split) * BB * DD * HW);
    int p0 = blockIdx.y * 32, c0 = blockIdx.z * 32;
    __shared__ float tl[32][33];
    int t = threadIdx.x;
    {
        int c = t >> 3, pg = t & 7;
        int p = p0 + pg * 4;
        if (p < HW) {
            float4 v = *(const float4*)(f + ((size_t)b * DD + c0 + c) * HW + p);
            tl[pg * 4 + 0][c] = v.x;
            tl[pg * 4 + 1][c] = v.y;
            tl[pg * 4 + 2][c] = v.z;
            tl[pg * 4 + 3][c] = v.w;
        }
    }
    __syncthreads();
    {
        int p = t >> 3, cg = t & 7;
        int gp = p0 + p;
        if (gp < HW) {
            int c = c0 + cg * 4;
            float4 pv = *(const float4*)(pe + (size_t)gp * DD + c);
            float4 o;
            o.x = tl[p][cg * 4 + 0] + pv.x * 1e-3f;
            o.y = tl[p][cg * 4 + 1] + pv.y * 1e-3f;
            o.z = tl[p][cg * 4 + 2] + pv.z * 1e-3f;
            o.w = tl[p][cg * 4 + 3] + pv.w * 1e-3f;
            size_t row = (mode == 0) ? ((size_t)b * LE + (size_t)img * HW + gp)
                                     : ((size_t)g * LDQ + gp);
            *(float4*)(xout + row * DD + c) = o;
        }
    }
}

// InstanceL2Norm: partial sums then apply (deterministic 2-stage)
__global__ void inorm_part(const float* __restrict__ in, float* __restrict__ part) {
    int g = blockIdx.x, q = blockIdx.y, t = threadIdx.x;
    const float4* ip = (const float4*)(in + (size_t)g * GRP) + (size_t)q * QF4;
    float ss = 0.0f;
    for (int i = t; i < QF4; i += 256) {
        float4 v = ip[i];
        ss += v.x * v.x + v.y * v.y + v.z * v.z + v.w * v.w;
    }
    __shared__ float red[8];
#pragma unroll
    for (int m = 16; m; m >>= 1) ss += __shfl_xor_sync(0xffffffffu, ss, m);
    if ((t & 31) == 0) red[t >> 5] = ss;
    __syncthreads();
    if (t == 0) {
        float s = 0.0f;
#pragma unroll
        for (int i = 0; i < 8; i++) s += red[i];
        part[g * 4 + q] = s;
    }
}

__global__ void inorm_apply(const float* __restrict__ in, float* __restrict__ out,
                            const float* __restrict__ part) {
    int g = blockIdx.x, q = blockIdx.y, t = threadIdx.x;
    float ss = part[g * 4 + 0] + part[g * 4 + 1] + part[g * 4 + 2] + part[g * 4 + 3];
    float sc = NSCALE * sqrtf(DHWF / (ss + IEPS));
    const float4* ip = (const float4*)(in + (size_t)g * GRP) + (size_t)q * QF4;
    float4* op = (float4*)(out + (size_t)g * GRP) + (size_t)q * QF4;
    for (int i = t; i < QF4; i += 256) {
        float4 v = ip[i];
        v.x *= sc; v.y *= sc; v.z *= sc; v.w *= sc;
        op[i] = v;
    }
}

// decoder 3-sum partials: u = x*mask, v = x + t3
__global__ void dec_part_kernel(const float* __restrict__ X, const float* __restrict__ XP,
                                const float* __restrict__ MASK, float* __restrict__ part) {
    int g = blockIdx.x, q = blockIdx.y, t = threadIdx.x;
    const float4* x4 = (const float4*)(X + (size_t)g * GRP);
    const float4* p4 = (const float4*)(XP + (size_t)g * GRP);
    const float* mk = MASK + (size_t)g * LDQ;
    float s2 = 0.0f, s4 = 0.0f, cr = 0.0f;
    for (int i = t; i < QF4; i += 256) {
        int gi = q * QF4 + i;
        float m = mk[gi >> 7];
        float4 x = x4[gi];
        float4 v = p4[gi];
        float ux = x.x * m, uy = x.y * m, uz = x.z * m, uw = x.w * m;
        s2 += ux * ux + uy * uy + uz * uz + uw * uw;
        s4 += v.x * v.x + v.y * v.y + v.z * v.z + v.w * v.w;
        cr += ux * v.x + uy * v.y + uz * v.z + uw * v.w;
    }
    __shared__ float r2[8], r4[8], rc[8];
#pragma unroll
    for (int m = 16; m; m >>= 1) {
        s2 += __shfl_xor_sync(0xffffffffu, s2, m);
        s4 += __shfl_xor_sync(0xffffffffu, s4, m);
        cr += __shfl_xor_sync(0xffffffffu, cr, m);
    }
    if ((t & 31) == 0) { r2[t >> 5] = s2; r4[t >> 5] = s4; rc[t >> 5] = cr; }
    __syncthreads();
    if (t == 0) {
        float a = 0, b = 0, c = 0;
#pragma unroll
        for (int i = 0; i < 8; i++) { a += r2[i]; b += r4[i]; c += rc[i]; }
        part[(g * 4 + q) * 3 + 0] = a;
        part[(g * 4 + q) * 3 + 1] = b;
        part[(g * 4 + q) * 3 + 2] = c;
    }
}

__global__ void dec_scale_kernel(const float* __restrict__ part, float* __restrict__ SC) {
    int g = threadIdx.x;
    if (g >= 96) return;
    float a = 0, b = 0, c = 0;
#pragma unroll
    for (int q = 0; q < 4; q++) {
        a += part[(g * 4 + q) * 3 + 0];
        b += part[(g * 4 + q) * 3 + 1];
        c += part[(g * 4 + q) * 3 + 2];
    }
    float S2 = NSCALE * sqrtf(DHWF / (a + IEPS));
    float S4 = NSCALE * sqrtf(DHWF / (b + IEPS));
    float sso = S2 * S2 * a + 2.0f * S2 * S4 * c + S4 * S4 * b;
    float SO = NSCALE * sqrtf(DHWF / (sso + IEPS));
    SC[g * 4 + 0] = S2;
    SC[g * 4 + 1] = S4;
    SC[g * 4 + 2] = SO;
}

// vectorized final combine + transpose: out[(g*512+c)*484+p]
__global__ void __launch_bounds__(256)
final_kernel(const float* __restrict__ X, const float* __restrict__ XP,
             const float* __restrict__ MASK, const float* __restrict__ SC,
             float* __restrict__ out) {
    int g = blockIdx.x;
    float S2 = SC[g * 4 + 0], S4 = SC[g * 4 + 1], SO = SC[g * 4 + 2];
    int p0 = blockIdx.y * 32, c0 = blockIdx.z * 32;
    __shared__ float tile[32][33];
    int t = threadIdx.x;
    size_t base = (size_t)g * GRP;
    // load: p = t>>3, cg = t&7; float4 along D
    {
        int p = t >> 3, cg = t & 7;
        int gp = p0 + p;
        if (gp < LDQ) {
            float m = MASK[(size_t)g * LDQ + gp];
            size_t idx = base + (size_t)gp * 512 + c0 + cg * 4;
            float4 x = *(const float4*)(X + idx);
            float4 v = *(const float4*)(XP + idx);
            tile[p][cg * 4 + 0] = SO * (S2 * (x.x * m) + S4 * v.x);
            tile[p][cg * 4 + 1] = SO * (S2 * (x.y * m) + S4 * v.y);
            tile[p][cg * 4 + 2] = SO * (S2 * (x.z * m) + S4 * v.z);
            tile[p][cg * 4 + 3] = SO * (S2 * (x.w * m) + S4 * v.w);
        }
    }
    __syncthreads();
    // store: c = t>>3, pg = t&7; float4 along HW (484 % 4 == 0)
    {
        int c = t >> 3, pg = t & 7;
        int p = p0 + pg * 4;
        if (p < LDQ) {
            float4 o;
            o.x = tile[pg * 4 + 0][c];
            o.y = tile[pg * 4 + 1][c];
            o.z = tile[pg * 4 + 2][c];
            o.w = tile[pg * 4 + 3][c];
            *(float4*)(out + ((size_t)g * 512 + c0 + c) * LDQ + p) = o;
        }
    }
}

// ================= launcher =================
extern "C" void kernel_launch(void* const* d_in, const int* in_sizes, int n_in,
                              void* d_out, int out_size) {
    const float* train_feat  = (const float*)d_in[0];
    const float* test_feat   = (const float*)d_in[1];
    const float* train_label = (const float*)d_in[2];
    const float* wk_self     = (const float*)d_in[3];
    const float* bk_self     = (const float*)d_in[4];
    const float* wk_cross    = (const float*)d_in[5];
    const float* bk_cross    = (const float*)d_in[6];
    float* out = (float*)d_out;

    float* base = nullptr;
    cudaGetSymbolAddress((void**)&base, g_scratch);
    float* pe     = base + OFF_PE;
    float* label  = base + OFF_LABEL;
    float* xe     = base + OFF_XE;
    float* dx0    = base + OFF_DX0;
    float* pq     = base + OFF_PQ;
    float* dpq    = base + OFF_DPQ;
    float* mem    = base + OFF_MEM;
    float* dx     = base + OFF_DX;
    float* pkc    = base + OFF_PKC;
    float* dpq2   = base + OFF_DPQ2;
    float* x1e    = base + OFF_X1E;
    float* dx1    = base + OFF_DX1;
    float* dxpt3  = base + OFF_DXPT3;
    float* dmask  = base + OFF_DMASK;
    float* dsc    = base + OFF_DSC;
    float* ipart  = base + OFF_IPART;
    float* dpart  = base + OFF_DPART;
    float* probs  = base + OFF_PROBS;

    const int MALL = 16 * LE + 96 * LDQ;

    pe_kernel<<<(HW * DD + 255) / 256, 256>>>(pe);
    label_kernel<<<(3 * BB * HW + 255) / 256, 256>>>(train_label, label);

    build_kernel<<<dim3(48, 16, 16), 256>>>(train_feat, train_feat, 3, pe, xe, 0);
    build_kernel<<<dim3(96, 16, 16), 256>>>(train_feat, test_feat, 3, pe, dx0, 1);

    // merged self projection [xe|dx0] -> [pq|dpq]
    tf32_proj_kernel<<<dim3(1, (MALL + 127) / 128, 1), 256>>>(xe, wk_self, pq, bk_self, MALL);

    // encoder
    tf32_logits_kernel<<<dim3(12, 12, 16), 256>>>(
        pq, pq, probs, LE, LE, 1456, LE,
        (size_t)LE * 128, (size_t)LE * 128, (size_t)LE * 1456, 0);
    tf32_value_kernel<<<dim3(4, 12, 16), 256>>>(
        probs, xe, xe, x1e, nullptr, nullptr, LE, 1456, LE, 1456,
        (size_t)LE * 1456, (size_t)LE * 512, (size_t)LE * 512, 0);
    inorm_part<<<dim3(48, 4), 256>>>(x1e, ipart);
    inorm_apply<<<dim3(48, 4), 256>>>(x1e, mem, ipart);

    // decoder self
    tf32_logits_kernel<<<dim3(4, 4, 96), 256>>>(
        dpq, dpq, probs, LDQ, LDQ, 496, LDQ,
        (size_t)LDQ * 128, (size_t)LDQ * 128, (size_t)LDQ * 496, 0);
    tf32_value_kernel<<<dim3(4, 4, 96), 256>>>(
        probs, dx0, dx0, dx1, nullptr, nullptr, LDQ, 496, LDQ, 496,
        (size_t)LDQ * 496, (size_t)LDQ * 512, (size_t)LDQ * 512, 0);
    inorm_part<<<dim3(96, 4), 256>>>(dx1, ipart);
    inorm_apply<<<dim3(96, 4), 256>>>(dx1, dx, ipart);

    // merged cross projection [mem|dx] -> [pkc|dpq2]
    tf32_proj_kernel<<<dim3(1, (MALL + 127) / 128, 1), 256>>>(mem, wk_cross, pkc, bk_cross, MALL);

    // cross attention (fused mask + label-weighted memory)
    tf32_logits_kernel<<<dim3(12, 4, 96), 256>>>(
        dpq2, pkc, probs, LDQ, LE, 1456, LE,
        (size_t)LDQ * 128, (size_t)LE * 128, (size_t)LDQ * 1456, 1);
    tf32_value_kernel<<<dim3(4, 4, 96), 256>>>(
        probs, mem, dx, dxpt3, label, dmask, LDQ, 1456, LE, 1456,
        (size_t)LDQ * 1456, (size_t)LE * 512, (size_t)LDQ * 512, 1);

    dec_part_kernel<<<dim3(96, 4), 256>>>(dx, dxpt3, dmask, dpart);
    dec_scale_kernel<<<1, 96>>>(dpart, dsc);
    final_kernel<<<dim3(96, 16, 16), 256>>>(dx, dxpt3, dmask, dsc, out);
}